// round 2
// baseline (speedup 1.0000x reference)
#include <cuda_runtime.h>

// Fused autoencoder forward + Jacobians, 2 samples/thread via fma.rn.f32x2.
// Outputs: theta[N,2] | J_h[N,2,2] | q_hat[N,2] | J_h_dec[N,2,2] | J_h_ana[N,2,2]

typedef unsigned long long pf;   // packed pair of f32 (lo = sample A, hi = sample B)

__device__ __forceinline__ pf pack2(float lo, float hi) {
    pf r; asm("mov.b64 %0, {%1, %2};" : "=l"(r) : "f"(lo), "f"(hi)); return r;
}
__device__ __forceinline__ float lo2(pf v) {
    float f; asm("{ .reg .b32 h; mov.b64 {%0, h}, %1; }" : "=f"(f) : "l"(v)); return f;
}
__device__ __forceinline__ float hi2(pf v) {
    float f; asm("{ .reg .b32 l; mov.b64 {l, %0}, %1; }" : "=f"(f) : "l"(v)); return f;
}
__device__ __forceinline__ pf ffma2(pf a, pf b, pf c) {
    pf d; asm("fma.rn.f32x2 %0, %1, %2, %3;" : "=l"(d) : "l"(a), "l"(b), "l"(c)); return d;
}
__device__ __forceinline__ pf fmul2(pf a, pf b) {
    pf d; asm("mul.rn.f32x2 %0, %1, %2;" : "=l"(d) : "l"(a), "l"(b)); return d;
}

// softplus h and sigmoid s, scalar. s = e^{z-h} = 2^{min(z,0)*log2e - lg2(1+e^{-|z|})}
__device__ __forceinline__ void act1(float z, float& h, float& s) {
    const float L2E = 1.442695041f, LN2 = 0.6931471806f;
    float t, g;
    asm("ex2.approx.ftz.f32 %0, %1;" : "=f"(t) : "f"(fabsf(z) * -L2E));   // e^{-|z|}
    asm("lg2.approx.ftz.f32 %0, %1;" : "=f"(g) : "f"(1.0f + t));          // lg2(1+t)
    h = fmaf(g, LN2, fmaxf(z, 0.0f));
    asm("ex2.approx.ftz.f32 %0, %1;" : "=f"(s) : "f"(fmaf(fminf(z, 0.0f), L2E, -g)));
}

__device__ __forceinline__ void act2(pf z, pf& hp, pf& sp) {
    float h0, s0, h1, s1;
    act1(lo2(z), h0, s0);
    act1(hi2(z), h1, s1);
    hp = pack2(h0, h1);
    sp = pack2(s0, s1);
}

// MLP 2->16->16->2 softplus, forward value + 2 tangent columns, packed over 2 samples.
__device__ __forceinline__ void mlp_jac2(
    pf x0, pf x1,
    const pf* __restrict__ W1, const pf* __restrict__ B1,
    const pf* __restrict__ W2, const pf* __restrict__ B2,
    const pf* __restrict__ W3, const pf* __restrict__ B3,
    pf& y0, pf& y1, pf& J00, pf& J01, pf& J10, pf& J11)
{
    pf h[16], ta[16], tb[16];
#pragma unroll
    for (int i = 0; i < 16; ++i) {
        pf w0 = W1[2 * i];
        pf w1 = W1[2 * i + 1];
        pf z  = ffma2(w0, x0, ffma2(w1, x1, B1[i]));
        pf hh, sp;
        act2(z, hh, sp);
        h[i]  = hh;
        ta[i] = fmul2(sp, w0);
        tb[i] = fmul2(sp, w1);
    }

    pf acc0 = B3[0], acc1 = B3[1];
    pf j00 = 0, j01 = 0, j10 = 0, j11 = 0;
#pragma unroll
    for (int j = 0; j < 16; ++j) {
        pf z = B2[j], a = 0, b = 0;
#pragma unroll
        for (int i = 0; i < 16; ++i) {
            pf w = W2[16 * j + i];
            z = ffma2(w, h[i],  z);
            a = ffma2(w, ta[i], a);
            b = ffma2(w, tb[i], b);
        }
        pf hh, sp;
        act2(z, hh, sp);
        pf sa  = fmul2(sp, a);
        pf sb  = fmul2(sp, b);
        pf w30 = W3[j];
        pf w31 = W3[16 + j];
        acc0 = ffma2(w30, hh, acc0);
        acc1 = ffma2(w31, hh, acc1);
        j00  = ffma2(w30, sa, j00);
        j01  = ffma2(w30, sb, j01);
        j10  = ffma2(w31, sa, j10);
        j11  = ffma2(w31, sb, j11);
    }
    y0 = acc0; y1 = acc1;
    J00 = j00; J01 = j01; J10 = j10; J11 = j11;
}

// shared layout (pf units)
#define S_EW1 0
#define S_EB1 32
#define S_EW2 48
#define S_EB2 304
#define S_EW3 320
#define S_EB3 352
#define S_DW1 354
#define S_DB1 386
#define S_DW2 402
#define S_DB2 658
#define S_DW3 674
#define S_DB3 706
#define S_TOT 708

__device__ __forceinline__ pf dup(float w) { return pack2(w, w); }

__global__ void __launch_bounds__(128, 3) ae_kernel(
    const float* __restrict__ q,
    const float* __restrict__ ew1, const float* __restrict__ eb1,
    const float* __restrict__ ew2, const float* __restrict__ eb2,
    const float* __restrict__ ew3, const float* __restrict__ eb3,
    const float* __restrict__ dw1, const float* __restrict__ db1,
    const float* __restrict__ dw2, const float* __restrict__ db2,
    const float* __restrict__ dw3, const float* __restrict__ db3,
    float* __restrict__ out, int N)
{
    __shared__ pf sm[S_TOT];

    const int t = threadIdx.x;
    if (t < 32) {
        sm[S_EW1 + t] = dup(ew1[t]);
        sm[S_DW1 + t] = dup(dw1[t]);
        sm[S_EW3 + t] = dup(ew3[t]);
        sm[S_DW3 + t] = dup(dw3[t]);
    } else if (t < 48) {
        int i = t - 32;
        sm[S_EB1 + i] = dup(eb1[i]);
        sm[S_DB1 + i] = dup(db1[i]);
        sm[S_EB2 + i] = dup(eb2[i]);
        sm[S_DB2 + i] = dup(db2[i]);
    } else if (t == 48) {
        sm[S_EB3 + 0] = dup(eb3[0]); sm[S_EB3 + 1] = dup(eb3[1]);
        sm[S_DB3 + 0] = dup(db3[0]); sm[S_DB3 + 1] = dup(db3[1]);
    }
#pragma unroll
    for (int i = t; i < 256; i += 128) {
        sm[S_EW2 + i] = dup(ew2[i]);
        sm[S_DW2 + i] = dup(dw2[i]);
    }
    __syncthreads();

    const int M = (N + 1) / 2;            // pair stride
    const int n = blockIdx.x * 128 + t;
    if (n >= M) return;
    const bool hasB = (n + M) < N;
    const int iA = n;
    const int iB = hasB ? (n + M) : n;    // degenerate pair for odd tail

    const float2 qa = reinterpret_cast<const float2*>(q)[iA];
    const float2 qb = reinterpret_cast<const float2*>(q)[iB];
    pf x0 = pack2(qa.x, qb.x);
    pf x1 = pack2(qa.y, qb.y);

    // analytic jacobian (scalar per lane)
    float ja[2][4];
#pragma unroll
    for (int l = 0; l < 2; ++l) {
        float q0 = l ? qb.x : qa.x;
        float q1 = l ? qb.y : qa.y;
        float r2  = fmaf(q0, q0, q1 * q1);
        float inv = __fdividef(1.0f, r2);
        float isr = rsqrtf(r2 + 1e-8f);
        ja[l][0] = -q1 * inv;
        ja[l][1] =  q0 * inv;
        ja[l][2] =  q0 * isr;
        ja[l][3] =  q1 * isr;
    }

    pf th0, th1, jh00, jh01, jh10, jh11;
    mlp_jac2(x0, x1, sm + S_EW1, sm + S_EB1, sm + S_EW2, sm + S_EB2,
             sm + S_EW3, sm + S_EB3, th0, th1, jh00, jh01, jh10, jh11);

    pf qh0, qh1, jd00, jd01, jd10, jd11;
    mlp_jac2(th0, th1, sm + S_DW1, sm + S_DB1, sm + S_DW2, sm + S_DB2,
             sm + S_DW3, sm + S_DB3, qh0, qh1, jd00, jd01, jd10, jd11);

    const size_t Ns = (size_t)N;
    float2* o_theta = reinterpret_cast<float2*>(out);
    float4* o_jh    = reinterpret_cast<float4*>(out + 2 * Ns);
    float2* o_qhat  = reinterpret_cast<float2*>(out + 6 * Ns);
    float4* o_jd    = reinterpret_cast<float4*>(out + 8 * Ns);
    float4* o_ja    = reinterpret_cast<float4*>(out + 12 * Ns);

    o_theta[iA] = make_float2(lo2(th0), lo2(th1));
    o_jh[iA]    = make_float4(lo2(jh00), lo2(jh01), lo2(jh10), lo2(jh11));
    o_qhat[iA]  = make_float2(lo2(qh0), lo2(qh1));
    o_jd[iA]    = make_float4(lo2(jd00), lo2(jd01), lo2(jd10), lo2(jd11));
    o_ja[iA]    = make_float4(ja[0][0], ja[0][1], ja[0][2], ja[0][3]);

    if (hasB) {
        o_theta[iB] = make_float2(hi2(th0), hi2(th1));
        o_jh[iB]    = make_float4(hi2(jh00), hi2(jh01), hi2(jh10), hi2(jh11));
        o_qhat[iB]  = make_float2(hi2(qh0), hi2(qh1));
        o_jd[iB]    = make_float4(hi2(jd00), hi2(jd01), hi2(jd10), hi2(jd11));
        o_ja[iB]    = make_float4(ja[1][0], ja[1][1], ja[1][2], ja[1][3]);
    }
}

extern "C" void kernel_launch(void* const* d_in, const int* in_sizes, int n_in,
                              void* d_out, int out_size) {
    const float* q   = (const float*)d_in[0];
    const float* ew1 = (const float*)d_in[1];
    const float* eb1 = (const float*)d_in[2];
    const float* ew2 = (const float*)d_in[3];
    const float* eb2 = (const float*)d_in[4];
    const float* ew3 = (const float*)d_in[5];
    const float* eb3 = (const float*)d_in[6];
    const float* dw1 = (const float*)d_in[7];
    const float* db1 = (const float*)d_in[8];
    const float* dw2 = (const float*)d_in[9];
    const float* db2 = (const float*)d_in[10];
    const float* dw3 = (const float*)d_in[11];
    const float* db3 = (const float*)d_in[12];

    const int N = in_sizes[0] / 2;
    const int M = (N + 1) / 2;
    const int blocks = (M + 127) / 128;
    ae_kernel<<<blocks, 128>>>(q, ew1, eb1, ew2, eb2, ew3, eb3,
                               dw1, db1, dw2, db2, dw3, db3,
                               (float*)d_out, N);
}

// round 3
// speedup vs baseline: 1.1882x; 1.1882x over previous
#include <cuda_runtime.h>

// Fused autoencoder forward + Jacobians (1 sample/thread, vectorized LDS).
// Outputs: theta[N,2] | J_h[N,2,2] | q_hat[N,2] | J_h_dec[N,2,2] | J_h_ana[N,2,2]

// softplus h and its derivative (sigmoid) s:
//   h = max(z,0) + ln(1+e^{-|z|})
//   s = e^{z-h} = 2^{min(z,0)*log2e - lg2(1+e^{-|z|})}
__device__ __forceinline__ void act(float z, float& h, float& s) {
    const float L2E = 1.442695041f, LN2 = 0.6931471806f;
    float t, g;
    asm("ex2.approx.ftz.f32 %0, %1;" : "=f"(t) : "f"(fabsf(z) * -L2E));  // e^{-|z|}
    asm("lg2.approx.ftz.f32 %0, %1;" : "=f"(g) : "f"(1.0f + t));         // lg2(1+t)
    h = fmaf(g, LN2, fmaxf(z, 0.0f));
    asm("ex2.approx.ftz.f32 %0, %1;" : "=f"(s) : "f"(fmaf(fminf(z, 0.0f), L2E, -g)));
}

// MLP 2->16->16->2 softplus; forward values + full 2x2 Jacobian via 2 tangent
// columns. Weight matrices read with float4 LDS (shared sections are 16B aligned).
__device__ __forceinline__ void mlp_jac(
    float x0, float x1,
    const float* __restrict__ W1, const float* __restrict__ B1,
    const float* __restrict__ W2, const float* __restrict__ B2,
    const float* __restrict__ W3, const float* __restrict__ B3,
    float& y0, float& y1,
    float& J00, float& J01, float& J10, float& J11)
{
    const float4* W1v = reinterpret_cast<const float4*>(W1);
    const float4* W2v = reinterpret_cast<const float4*>(W2);

    float h[16], ta[16], tb[16];
#pragma unroll
    for (int p = 0; p < 8; ++p) {            // two hidden units per float4
        float4 w = W1v[p];
        {
            int i = 2 * p;
            float z = fmaf(w.x, x0, fmaf(w.y, x1, B1[i]));
            float hh, s;
            act(z, hh, s);
            h[i] = hh; ta[i] = s * w.x; tb[i] = s * w.y;
        }
        {
            int i = 2 * p + 1;
            float z = fmaf(w.z, x0, fmaf(w.w, x1, B1[i]));
            float hh, s;
            act(z, hh, s);
            h[i] = hh; ta[i] = s * w.z; tb[i] = s * w.w;
        }
    }

    float acc0 = B3[0], acc1 = B3[1];
    float j00 = 0.f, j01 = 0.f, j10 = 0.f, j11 = 0.f;
#pragma unroll
    for (int j = 0; j < 16; ++j) {
        float z = B2[j], a = 0.f, b = 0.f;
#pragma unroll
        for (int p = 0; p < 4; ++p) {
            float4 w = W2v[4 * j + p];
            int i = 4 * p;
            z = fmaf(w.x, h[i+0], z); a = fmaf(w.x, ta[i+0], a); b = fmaf(w.x, tb[i+0], b);
            z = fmaf(w.y, h[i+1], z); a = fmaf(w.y, ta[i+1], a); b = fmaf(w.y, tb[i+1], b);
            z = fmaf(w.z, h[i+2], z); a = fmaf(w.z, ta[i+2], a); b = fmaf(w.z, tb[i+2], b);
            z = fmaf(w.w, h[i+3], z); a = fmaf(w.w, ta[i+3], a); b = fmaf(w.w, tb[i+3], b);
        }
        float hh, s;
        act(z, hh, s);
        float sa = s * a;
        float sb = s * b;
        float w30 = W3[j];
        float w31 = W3[16 + j];
        acc0 = fmaf(w30, hh, acc0);
        acc1 = fmaf(w31, hh, acc1);
        j00  = fmaf(w30, sa, j00);
        j01  = fmaf(w30, sb, j01);
        j10  = fmaf(w31, sa, j10);
        j11  = fmaf(w31, sb, j11);
    }
    y0 = acc0; y1 = acc1;
    J00 = j00; J01 = j01; J10 = j10; J11 = j11;
}

// shared layout (floats, every section 16B aligned)
#define S_EW1 0
#define S_EB1 32
#define S_EW2 48
#define S_EB2 304
#define S_EW3 320
#define S_EB3 352   // 2 floats + 2 pad
#define S_DW1 356
#define S_DB1 388
#define S_DW2 404
#define S_DB2 660
#define S_DW3 676
#define S_DB3 708   // 2 floats + 2 pad
#define S_TOT 712

__global__ void __launch_bounds__(256) ae_kernel(
    const float* __restrict__ q,
    const float* __restrict__ ew1, const float* __restrict__ eb1,
    const float* __restrict__ ew2, const float* __restrict__ eb2,
    const float* __restrict__ ew3, const float* __restrict__ eb3,
    const float* __restrict__ dw1, const float* __restrict__ db1,
    const float* __restrict__ dw2, const float* __restrict__ db2,
    const float* __restrict__ dw3, const float* __restrict__ db3,
    float* __restrict__ out, int N)
{
    __shared__ __align__(16) float sm[S_TOT];

    const int t = threadIdx.x;
    if (t < 32) {
        sm[S_EW1 + t] = ew1[t];
        sm[S_DW1 + t] = dw1[t];
        sm[S_EW3 + t] = ew3[t];
        sm[S_DW3 + t] = dw3[t];
    } else if (t < 48) {
        int i = t - 32;
        sm[S_EB1 + i] = eb1[i];
        sm[S_DB1 + i] = db1[i];
        sm[S_EB2 + i] = eb2[i];
        sm[S_DB2 + i] = db2[i];
    } else if (t == 48) {
        sm[S_EB3 + 0] = eb3[0]; sm[S_EB3 + 1] = eb3[1];
        sm[S_DB3 + 0] = db3[0]; sm[S_DB3 + 1] = db3[1];
    }
    sm[S_EW2 + t] = ew2[t];   // blockDim == 256
    sm[S_DW2 + t] = dw2[t];
    __syncthreads();

    const int n = blockIdx.x * 256 + t;
    if (n >= N) return;

    const float2 qv = reinterpret_cast<const float2*>(q)[n];
    const float q0 = qv.x, q1 = qv.y;

    // analytic jacobian
    const float r2  = fmaf(q0, q0, q1 * q1);
    const float inv = __fdividef(1.0f, r2);
    const float isr = rsqrtf(r2 + 1e-8f);
    const float ja00 = -q1 * inv;
    const float ja01 =  q0 * inv;
    const float ja10 =  q0 * isr;
    const float ja11 =  q1 * isr;

    float th0, th1, jh00, jh01, jh10, jh11;
    mlp_jac(q0, q1, sm + S_EW1, sm + S_EB1, sm + S_EW2, sm + S_EB2,
            sm + S_EW3, sm + S_EB3, th0, th1, jh00, jh01, jh10, jh11);

    float qh0, qh1, jd00, jd01, jd10, jd11;
    mlp_jac(th0, th1, sm + S_DW1, sm + S_DB1, sm + S_DW2, sm + S_DB2,
            sm + S_DW3, sm + S_DB3, qh0, qh1, jd00, jd01, jd10, jd11);

    const size_t Ns = (size_t)N;
    float2* o_theta = reinterpret_cast<float2*>(out);
    float4* o_jh    = reinterpret_cast<float4*>(out + 2 * Ns);
    float2* o_qhat  = reinterpret_cast<float2*>(out + 6 * Ns);
    float4* o_jd    = reinterpret_cast<float4*>(out + 8 * Ns);
    float4* o_ja    = reinterpret_cast<float4*>(out + 12 * Ns);

    o_theta[n] = make_float2(th0, th1);
    o_jh[n]    = make_float4(jh00, jh01, jh10, jh11);
    o_qhat[n]  = make_float2(qh0, qh1);
    o_jd[n]    = make_float4(jd00, jd01, jd10, jd11);
    o_ja[n]    = make_float4(ja00, ja01, ja10, ja11);
}

extern "C" void kernel_launch(void* const* d_in, const int* in_sizes, int n_in,
                              void* d_out, int out_size) {
    const float* q   = (const float*)d_in[0];
    const float* ew1 = (const float*)d_in[1];
    const float* eb1 = (const float*)d_in[2];
    const float* ew2 = (const float*)d_in[3];
    const float* eb2 = (const float*)d_in[4];
    const float* ew3 = (const float*)d_in[5];
    const float* eb3 = (const float*)d_in[6];
    const float* dw1 = (const float*)d_in[7];
    const float* db1 = (const float*)d_in[8];
    const float* dw2 = (const float*)d_in[9];
    const float* db2 = (const float*)d_in[10];
    const float* dw3 = (const float*)d_in[11];
    const float* db3 = (const float*)d_in[12];

    const int N = in_sizes[0] / 2;
    const int blocks = (N + 255) / 256;
    ae_kernel<<<blocks, 256>>>(q, ew1, eb1, ew2, eb2, ew3, eb3,
                               dw1, db1, dw2, db2, dw3, db3,
                               (float*)d_out, N);
}

// round 4
// speedup vs baseline: 1.2214x; 1.0279x over previous
#include <cuda_runtime.h>

// Fused autoencoder forward + Jacobians, 2 samples/thread via fma.rn.f32x2,
// weights as duplicated (w,w) pairs in __constant__ (-> LDCU / uniform regs,
// keeping FFMA2 at 2 distinct GPR bank reads -> rt=2).
// Outputs: theta[N,2] | J_h[N,2,2] | q_hat[N,2] | J_h_dec[N,2,2] | J_h_ana[N,2,2]

typedef unsigned long long pf;   // packed pair of f32 (lo = sample A, hi = sample B)

// constant layout (pf units)
#define S_EW1 0
#define S_EB1 32
#define S_EW2 48
#define S_EB2 304
#define S_EW3 320
#define S_EB3 352
#define S_DW1 354
#define S_DB1 386
#define S_DW2 402
#define S_DB2 658
#define S_DW3 674
#define S_DB3 706
#define S_TOT 708

__constant__ pf CW[S_TOT];
__device__ pf g_scratch[S_TOT];

__device__ __forceinline__ pf pack2(float lo, float hi) {
    pf r; asm("mov.b64 %0, {%1, %2};" : "=l"(r) : "f"(lo), "f"(hi)); return r;
}
__device__ __forceinline__ float lo2(pf v) {
    float f; asm("{ .reg .b32 h; mov.b64 {%0, h}, %1; }" : "=f"(f) : "l"(v)); return f;
}
__device__ __forceinline__ float hi2(pf v) {
    float f; asm("{ .reg .b32 l; mov.b64 {l, %0}, %1; }" : "=f"(f) : "l"(v)); return f;
}
__device__ __forceinline__ pf ffma2(pf a, pf b, pf c) {
    pf d; asm("fma.rn.f32x2 %0, %1, %2, %3;" : "=l"(d) : "l"(a), "l"(b), "l"(c)); return d;
}
__device__ __forceinline__ pf fmul2(pf a, pf b) {
    pf d; asm("mul.rn.f32x2 %0, %1, %2;" : "=l"(d) : "l"(a), "l"(b)); return d;
}
__device__ __forceinline__ float ex2f(float x) {
    float r; asm("ex2.approx.ftz.f32 %0, %1;" : "=f"(r) : "f"(x)); return r;
}
__device__ __forceinline__ float lg2f(float x) {
    float r; asm("lg2.approx.ftz.f32 %0, %1;" : "=f"(r) : "f"(x)); return r;
}

// Packed softplus + sigmoid. Pre-activations here are bounded (|z| <~ 13 given
// U(-0.25,0.25) weights and N(0,1) inputs), so the direct form is safe:
//   t = 2^(z*log2e); h = ln(1+t) = lg2(1+t)*ln2; s = t/(1+t) = 2^(z*log2e - lg2(1+t))
__device__ __forceinline__ void act2(pf z, pf& h, pf& s) {
    const float LN2 = 0.6931471806f;
    const pf L2E2 = pack2(1.442695041f, 1.442695041f);
    pf zl = fmul2(z, L2E2);
    float t0 = ex2f(lo2(zl));
    float t1 = ex2f(hi2(zl));
    float g0 = lg2f(1.0f + t0);
    float g1 = lg2f(1.0f + t1);
    h = pack2(g0 * LN2, g1 * LN2);
    s = pack2(ex2f(lo2(zl) - g0), ex2f(hi2(zl) - g1));
}

// MLP 2->16->16->2 softplus; packed over 2 samples; weights from __constant__.
template<int W1O, int B1O, int W2O, int B2O, int W3O, int B3O>
__device__ __forceinline__ void mlp_jac2(
    pf x0, pf x1,
    pf& y0, pf& y1, pf& J00, pf& J01, pf& J10, pf& J11)
{
    pf h[16], ta[16], tb[16];
#pragma unroll
    for (int i = 0; i < 16; ++i) {
        pf w0 = CW[W1O + 2 * i];
        pf w1 = CW[W1O + 2 * i + 1];
        pf z  = ffma2(w0, x0, ffma2(w1, x1, CW[B1O + i]));
        pf hh, sp;
        act2(z, hh, sp);
        h[i]  = hh;
        ta[i] = fmul2(sp, w0);
        tb[i] = fmul2(sp, w1);
    }

    pf acc0 = CW[B3O], acc1 = CW[B3O + 1];
    pf j00 = 0, j01 = 0, j10 = 0, j11 = 0;
#pragma unroll
    for (int j = 0; j < 16; ++j) {
        pf z = CW[B2O + j], a = 0, b = 0;
#pragma unroll
        for (int i = 0; i < 16; ++i) {
            pf w = CW[W2O + 16 * j + i];
            z = ffma2(w, h[i],  z);
            a = ffma2(w, ta[i], a);
            b = ffma2(w, tb[i], b);
        }
        pf hh, sp;
        act2(z, hh, sp);
        pf sa  = fmul2(sp, a);
        pf sb  = fmul2(sp, b);
        pf w30 = CW[W3O + j];
        pf w31 = CW[W3O + 16 + j];
        acc0 = ffma2(w30, hh, acc0);
        acc1 = ffma2(w31, hh, acc1);
        j00  = ffma2(w30, sa, j00);
        j01  = ffma2(w30, sb, j01);
        j10  = ffma2(w31, sa, j10);
        j11  = ffma2(w31, sb, j11);
    }
    y0 = acc0; y1 = acc1;
    J00 = j00; J01 = j01; J10 = j10; J11 = j11;
}

__device__ __forceinline__ pf dupw(float w) { return pack2(w, w); }

__global__ void __launch_bounds__(256) prep_kernel(
    const float* __restrict__ ew1, const float* __restrict__ eb1,
    const float* __restrict__ ew2, const float* __restrict__ eb2,
    const float* __restrict__ ew3, const float* __restrict__ eb3,
    const float* __restrict__ dw1, const float* __restrict__ db1,
    const float* __restrict__ dw2, const float* __restrict__ db2,
    const float* __restrict__ dw3, const float* __restrict__ db3)
{
    const int t = threadIdx.x;
    if (t < 32) {
        g_scratch[S_EW1 + t] = dupw(ew1[t]);
        g_scratch[S_DW1 + t] = dupw(dw1[t]);
        g_scratch[S_EW3 + t] = dupw(ew3[t]);
        g_scratch[S_DW3 + t] = dupw(dw3[t]);
    } else if (t < 48) {
        int i = t - 32;
        g_scratch[S_EB1 + i] = dupw(eb1[i]);
        g_scratch[S_DB1 + i] = dupw(db1[i]);
        g_scratch[S_EB2 + i] = dupw(eb2[i]);
        g_scratch[S_DB2 + i] = dupw(db2[i]);
    } else if (t == 48) {
        g_scratch[S_EB3 + 0] = dupw(eb3[0]); g_scratch[S_EB3 + 1] = dupw(eb3[1]);
        g_scratch[S_DB3 + 0] = dupw(db3[0]); g_scratch[S_DB3 + 1] = dupw(db3[1]);
    }
    g_scratch[S_EW2 + t] = dupw(ew2[t]);
    g_scratch[S_DW2 + t] = dupw(dw2[t]);
}

__global__ void __launch_bounds__(128, 3) ae_kernel(
    const float* __restrict__ q, float* __restrict__ out, int N)
{
    const int M = (N + 1) / 2;            // pair stride
    const int n = blockIdx.x * 128 + threadIdx.x;
    if (n >= M) return;
    const bool hasB = (n + M) < N;
    const int iA = n;
    const int iB = hasB ? (n + M) : n;

    const float2 qa = reinterpret_cast<const float2*>(q)[iA];
    const float2 qb = reinterpret_cast<const float2*>(q)[iB];
    pf x0 = pack2(qa.x, qb.x);
    pf x1 = pack2(qa.y, qb.y);

    // analytic jacobian (scalar per lane)
    float ja[2][4];
#pragma unroll
    for (int l = 0; l < 2; ++l) {
        float q0 = l ? qb.x : qa.x;
        float q1 = l ? qb.y : qa.y;
        float r2  = fmaf(q0, q0, q1 * q1);
        float inv = __fdividef(1.0f, r2);
        float isr = rsqrtf(r2 + 1e-8f);
        ja[l][0] = -q1 * inv;
        ja[l][1] =  q0 * inv;
        ja[l][2] =  q0 * isr;
        ja[l][3] =  q1 * isr;
    }

    pf th0, th1, jh00, jh01, jh10, jh11;
    mlp_jac2<S_EW1, S_EB1, S_EW2, S_EB2, S_EW3, S_EB3>(
        x0, x1, th0, th1, jh00, jh01, jh10, jh11);

    pf qh0, qh1, jd00, jd01, jd10, jd11;
    mlp_jac2<S_DW1, S_DB1, S_DW2, S_DB2, S_DW3, S_DB3>(
        th0, th1, qh0, qh1, jd00, jd01, jd10, jd11);

    const size_t Ns = (size_t)N;
    float2* o_theta = reinterpret_cast<float2*>(out);
    float4* o_jh    = reinterpret_cast<float4*>(out + 2 * Ns);
    float2* o_qhat  = reinterpret_cast<float2*>(out + 6 * Ns);
    float4* o_jd    = reinterpret_cast<float4*>(out + 8 * Ns);
    float4* o_ja    = reinterpret_cast<float4*>(out + 12 * Ns);

    o_theta[iA] = make_float2(lo2(th0), lo2(th1));
    o_jh[iA]    = make_float4(lo2(jh00), lo2(jh01), lo2(jh10), lo2(jh11));
    o_qhat[iA]  = make_float2(lo2(qh0), lo2(qh1));
    o_jd[iA]    = make_float4(lo2(jd00), lo2(jd01), lo2(jd10), lo2(jd11));
    o_ja[iA]    = make_float4(ja[0][0], ja[0][1], ja[0][2], ja[0][3]);

    if (hasB) {
        o_theta[iB] = make_float2(hi2(th0), hi2(th1));
        o_jh[iB]    = make_float4(hi2(jh00), hi2(jh01), hi2(jh10), hi2(jh11));
        o_qhat[iB]  = make_float2(hi2(qh0), hi2(qh1));
        o_jd[iB]    = make_float4(hi2(jd00), hi2(jd01), hi2(jd10), hi2(jd11));
        o_ja[iB]    = make_float4(ja[1][0], ja[1][1], ja[1][2], ja[1][3]);
    }
}

extern "C" void kernel_launch(void* const* d_in, const int* in_sizes, int n_in,
                              void* d_out, int out_size) {
    const float* q   = (const float*)d_in[0];

    prep_kernel<<<1, 256>>>(
        (const float*)d_in[1], (const float*)d_in[2],
        (const float*)d_in[3], (const float*)d_in[4],
        (const float*)d_in[5], (const float*)d_in[6],
        (const float*)d_in[7], (const float*)d_in[8],
        (const float*)d_in[9], (const float*)d_in[10],
        (const float*)d_in[11], (const float*)d_in[12]);

    // D2D copy scratch -> __constant__ (graph-capturable memcpy node)
    void* cw_addr = nullptr;
    void* sc_addr = nullptr;
    cudaGetSymbolAddress(&cw_addr, CW);
    cudaGetSymbolAddress(&sc_addr, g_scratch);
    cudaMemcpyAsync(cw_addr, sc_addr, S_TOT * sizeof(pf),
                    cudaMemcpyDeviceToDevice, 0);

    const int N = in_sizes[0] / 2;
    const int M = (N + 1) / 2;
    const int blocks = (M + 127) / 128;
    ae_kernel<<<blocks, 128>>>(q, (float*)d_out, N);
}

// round 5
// speedup vs baseline: 1.3921x; 1.1398x over previous
#include <cuda_runtime.h>

// Fused autoencoder forward + Jacobians.
// 1 sample/thread; scalar value chain + f32x2-packed tangent pair (ta,tb).
// Weights live in __constant__ (LDCU/uniform path): W1 as natural (w0,w1)
// pairs, W2/W3 as duplicated (w,w) pairs so one LDCU.64 feeds both the scalar
// FFMA (lo lane) and the packed FFMA2.
// Outputs: theta[N,2] | J_h[N,2,2] | q_hat[N,2] | J_h_dec[N,2,2] | J_h_ana[N,2,2]

typedef unsigned long long pf;   // packed (lo,hi) pair of f32

struct CData {
    float2 w2d[2][256];   // dup (w,w), [enc|dec], row-major 16x16
    float2 w3d[2][32];    // dup (w,w)
    float2 w1p[2][16];    // natural (w0,w1) rows of W1
    float  b1[2][16];
    float  b2[2][16];
    float  b3[2][2];
};

__constant__ CData CW;
__device__   CData g_scratch;

__device__ __forceinline__ pf pack2(float lo, float hi) {
    pf r; asm("mov.b64 %0, {%1, %2};" : "=l"(r) : "f"(lo), "f"(hi)); return r;
}
__device__ __forceinline__ pf asp(float2 v) {
    pf r; asm("mov.b64 %0, {%1, %2};" : "=l"(r) : "f"(v.x), "f"(v.y)); return r;
}
__device__ __forceinline__ pf ffma2(pf a, pf b, pf c) {
    pf d; asm("fma.rn.f32x2 %0, %1, %2, %3;" : "=l"(d) : "l"(a), "l"(b), "l"(c)); return d;
}
__device__ __forceinline__ pf fmul2(pf a, pf b) {
    pf d; asm("mul.rn.f32x2 %0, %1, %2;" : "=l"(d) : "l"(a), "l"(b)); return d;
}

// softplus h and sigmoid s (stable, 3 MUFU):
//   h = max(z,0) + lg2(1+e^{-|z|})*ln2 ; s = 2^{min(z,0)*log2e - lg2(1+e^{-|z|})}
__device__ __forceinline__ void act(float z, float& h, float& s) {
    const float L2E = 1.442695041f, LN2 = 0.6931471806f;
    float t, g;
    asm("ex2.approx.ftz.f32 %0, %1;" : "=f"(t) : "f"(fabsf(z) * -L2E));
    asm("lg2.approx.ftz.f32 %0, %1;" : "=f"(g) : "f"(1.0f + t));
    h = fmaf(g, LN2, fmaxf(z, 0.0f));
    asm("ex2.approx.ftz.f32 %0, %1;" : "=f"(s) : "f"(fmaf(fminf(z, 0.0f), L2E, -g)));
}

// MLP 2->16->16->2 softplus. Forward values scalar; Jacobian rows returned as
// packed pairs rj0=(J00,J01), rj1=(J10,J11).  E=0 encoder, E=1 decoder.
template<int E>
__device__ __forceinline__ void mlp_jac(
    float x0, float x1,
    float& y0, float& y1, pf& rj0, pf& rj1)
{
    float h[16];
    pf tab[16];
#pragma unroll
    for (int i = 0; i < 16; ++i) {
        float2 w = CW.w1p[E][i];
        float z = fmaf(w.x, x0, fmaf(w.y, x1, CW.b1[E][i]));
        float hh, s;
        act(z, hh, s);
        h[i]   = hh;
        tab[i] = fmul2(pack2(s, s), asp(w));   // (ta,tb) = s*(w0,w1)
    }

    float acc0 = CW.b3[E][0], acc1 = CW.b3[E][1];
    pf j0 = 0, j1 = 0;                          // (J00,J01), (J10,J11)
#pragma unroll
    for (int j = 0; j < 16; ++j) {
        float z = CW.b2[E][j];
        pf ab = 0;
#pragma unroll
        for (int i = 0; i < 16; ++i) {
            float2 w = CW.w2d[E][16 * j + i];   // (w,w)
            z  = fmaf(w.x, h[i], z);
            ab = ffma2(asp(w), tab[i], ab);
        }
        float hh, s;
        act(z, hh, s);
        pf sab = fmul2(pack2(s, s), ab);        // (s*a, s*b)
        float2 w30 = CW.w3d[E][j];
        float2 w31 = CW.w3d[E][16 + j];
        acc0 = fmaf(w30.x, hh, acc0);
        acc1 = fmaf(w31.x, hh, acc1);
        j0 = ffma2(asp(w30), sab, j0);
        j1 = ffma2(asp(w31), sab, j1);
    }
    y0 = acc0; y1 = acc1; rj0 = j0; rj1 = j1;
}

__global__ void __launch_bounds__(256) prep_kernel(
    const float* __restrict__ ew1, const float* __restrict__ eb1,
    const float* __restrict__ ew2, const float* __restrict__ eb2,
    const float* __restrict__ ew3, const float* __restrict__ eb3,
    const float* __restrict__ dw1, const float* __restrict__ db1,
    const float* __restrict__ dw2, const float* __restrict__ db2,
    const float* __restrict__ dw3, const float* __restrict__ db3)
{
    const int t = threadIdx.x;
    g_scratch.w2d[0][t] = make_float2(ew2[t], ew2[t]);
    g_scratch.w2d[1][t] = make_float2(dw2[t], dw2[t]);
    if (t < 32) {
        g_scratch.w3d[0][t] = make_float2(ew3[t], ew3[t]);
        g_scratch.w3d[1][t] = make_float2(dw3[t], dw3[t]);
    }
    if (t < 16) {
        g_scratch.w1p[0][t] = make_float2(ew1[2 * t], ew1[2 * t + 1]);
        g_scratch.w1p[1][t] = make_float2(dw1[2 * t], dw1[2 * t + 1]);
        g_scratch.b1[0][t] = eb1[t];
        g_scratch.b1[1][t] = db1[t];
        g_scratch.b2[0][t] = eb2[t];
        g_scratch.b2[1][t] = db2[t];
    }
    if (t < 2) {
        g_scratch.b3[0][t] = eb3[t];
        g_scratch.b3[1][t] = db3[t];
    }
}

__global__ void __launch_bounds__(256) ae_kernel(
    const float* __restrict__ q, float* __restrict__ out, int N)
{
    const int n = blockIdx.x * 256 + threadIdx.x;
    if (n >= N) return;

    const float2 qv = reinterpret_cast<const float2*>(q)[n];
    const float q0 = qv.x, q1 = qv.y;

    // analytic jacobian
    const float r2  = fmaf(q0, q0, q1 * q1);
    const float inv = __fdividef(1.0f, r2);
    const float isr = rsqrtf(r2 + 1e-8f);
    const float ja00 = -q1 * inv;
    const float ja01 =  q0 * inv;
    const float ja10 =  q0 * isr;
    const float ja11 =  q1 * isr;

    float th0, th1, qh0, qh1;
    pf jh0, jh1, jd0, jd1;
    mlp_jac<0>(q0, q1, th0, th1, jh0, jh1);
    mlp_jac<1>(th0, th1, qh0, qh1, jd0, jd1);

    const size_t Ns = (size_t)N;
    float2* o_theta = reinterpret_cast<float2*>(out);
    pf*     o_jh    = reinterpret_cast<pf*>(out + 2 * Ns);
    float2* o_qhat  = reinterpret_cast<float2*>(out + 6 * Ns);
    pf*     o_jd    = reinterpret_cast<pf*>(out + 8 * Ns);
    float4* o_ja    = reinterpret_cast<float4*>(out + 12 * Ns);

    o_theta[n]      = make_float2(th0, th1);
    o_jh[2 * n]     = jh0;               // (J00,J01)
    o_jh[2 * n + 1] = jh1;               // (J10,J11)
    o_qhat[n]       = make_float2(qh0, qh1);
    o_jd[2 * n]     = jd0;
    o_jd[2 * n + 1] = jd1;
    o_ja[n]         = make_float4(ja00, ja01, ja10, ja11);
}

extern "C" void kernel_launch(void* const* d_in, const int* in_sizes, int n_in,
                              void* d_out, int out_size) {
    const float* q = (const float*)d_in[0];

    prep_kernel<<<1, 256>>>(
        (const float*)d_in[1], (const float*)d_in[2],
        (const float*)d_in[3], (const float*)d_in[4],
        (const float*)d_in[5], (const float*)d_in[6],
        (const float*)d_in[7], (const float*)d_in[8],
        (const float*)d_in[9], (const float*)d_in[10],
        (const float*)d_in[11], (const float*)d_in[12]);

    void* cw_addr = nullptr;
    void* sc_addr = nullptr;
    cudaGetSymbolAddress(&cw_addr, CW);
    cudaGetSymbolAddress(&sc_addr, g_scratch);
    cudaMemcpyAsync(cw_addr, sc_addr, sizeof(CData),
                    cudaMemcpyDeviceToDevice, 0);

    const int N = in_sizes[0] / 2;
    const int blocks = (N + 255) / 256;
    ae_kernel<<<blocks, 256>>>(q, (float*)d_out, N);
}